// round 2
// baseline (speedup 1.0000x reference)
#include <cuda_runtime.h>
#include <cstdint>
#include <math.h>

#define D    128
#define S_MAX 125000
#define EPS  1e-13f

// Scratch (static device globals -- no allocation)
__device__ float g_y[(size_t)S_MAX * D];   // 64 MB: per-segment weighted sum of x
__device__ float g_sg[S_MAX];              // per-segment sum of normalized gates
__device__ int   g_starts[S_MAX + 1];      // segment start offsets

// ---------------------------------------------------------------------------
// Kernel 1: segment start offsets from the sorted index array.
// g_starts[s] = first n with index[n] >= s; g_starts[S] = N.
// Each s is written by exactly one thread (disjoint intervals).
// ---------------------------------------------------------------------------
__global__ void seg_starts_kernel(const int* __restrict__ idx, int N, int S) {
    int n = blockIdx.x * blockDim.x + threadIdx.x;
    if (n >= N) return;
    int cur  = idx[n];
    int prev = (n == 0) ? -1 : idx[n - 1];
    for (int s = prev + 1; s <= cur; ++s) g_starts[s] = n;
    if (n == N - 1) {
        for (int s = cur + 1; s <= S; ++s) g_starts[s] = N;
    }
}

__device__ __forceinline__ float warp_sum(float v) {
    v += __shfl_xor_sync(0xffffffffu, v, 16);
    v += __shfl_xor_sync(0xffffffffu, v, 8);
    v += __shfl_xor_sync(0xffffffffu, v, 4);
    v += __shfl_xor_sync(0xffffffffu, v, 2);
    v += __shfl_xor_sync(0xffffffffu, v, 1);
    return v;
}

__device__ __forceinline__ float dot4(float4 a, float4 b) {
    return a.x * b.x + a.y * b.y + a.z * b.z + a.w * b.w;
}

// ---------------------------------------------------------------------------
// Kernel 2: fused gate + softmax-normalize + weighted segment aggregation.
// One warp per segment. Lane l covers columns [4l, 4l+4) (one float4).
// Pass A: gate_r = dot(x_r, Wg)+bg (warp reduce); g_r = w_r * exp(gate_r);
//         denom = sum g_r.  g_r stashed at lane (r - r0) (len <= 32 fast path).
// Pass B: y_s += (g_r/denom) * x_r  (rows re-read; L1-hot).
// sg_s = denom/(denom+eps).  No atomics, no pre-zeroing needed.
// ---------------------------------------------------------------------------
__global__ void agg_kernel(const float* __restrict__ x,
                           const float* __restrict__ w,
                           const float* __restrict__ Wg,
                           const float* __restrict__ bgp,
                           int S) {
    int warp = (int)((blockIdx.x * (unsigned)blockDim.x + threadIdx.x) >> 5);
    if (warp >= S) return;
    int lane = threadIdx.x & 31;

    int r0 = g_starts[warp];
    int r1 = g_starts[warp + 1];
    int len = r1 - r0;

    float4 wg  = *(const float4*)(Wg + lane * 4);
    float  bg0 = bgp[0];
    const float* xb = x + (size_t)r0 * D + lane * 4;

    float denom = 0.f;
    float gl = 0.f;                     // lane (r-r0) holds g for row r

    if (len <= 32) {
        // ---- Pass A: gates + denom (chunks of 4 rows for MLP) ----
        for (int base = 0; base < len; base += 4) {
            float4 v0 = make_float4(0.f,0.f,0.f,0.f), v1 = v0, v2 = v0, v3 = v0;
            float w0 = 0.f, w1 = 0.f, w2 = 0.f, w3 = 0.f;
            if (base + 0 < len) { v0 = *(const float4*)(xb + (size_t)(base + 0) * D); w0 = w[r0 + base + 0]; }
            if (base + 1 < len) { v1 = *(const float4*)(xb + (size_t)(base + 1) * D); w1 = w[r0 + base + 1]; }
            if (base + 2 < len) { v2 = *(const float4*)(xb + (size_t)(base + 2) * D); w2 = w[r0 + base + 2]; }
            if (base + 3 < len) { v3 = *(const float4*)(xb + (size_t)(base + 3) * D); w3 = w[r0 + base + 3]; }
            float p0 = warp_sum(dot4(v0, wg));
            float p1 = warp_sum(dot4(v1, wg));
            float p2 = warp_sum(dot4(v2, wg));
            float p3 = warp_sum(dot4(v3, wg));
            float g0 = (base + 0 < len) ? w0 * expf(p0 + bg0) : 0.f;
            float g1 = (base + 1 < len) ? w1 * expf(p1 + bg0) : 0.f;
            float g2 = (base + 2 < len) ? w2 * expf(p2 + bg0) : 0.f;
            float g3 = (base + 3 < len) ? w3 * expf(p3 + bg0) : 0.f;
            denom += g0 + g1 + g2 + g3;
            if (lane == base + 0) gl = g0;
            if (lane == base + 1) gl = g1;
            if (lane == base + 2) gl = g2;
            if (lane == base + 3) gl = g3;
        }
        float inv = 1.f / (denom + EPS);
        // ---- Pass B: weighted accumulation (rows L1-hot) ----
        float4 acc = make_float4(0.f,0.f,0.f,0.f);
        for (int base = 0; base < len; base += 4) {
            #pragma unroll
            for (int j = 0; j < 4; ++j) {
                float gj = __shfl_sync(0xffffffffu, gl, base + j);
                if (base + j < len) {
                    float4 v = *(const float4*)(xb + (size_t)(base + j) * D);
                    float c = gj * inv;
                    acc.x += c * v.x; acc.y += c * v.y;
                    acc.z += c * v.z; acc.w += c * v.w;
                }
            }
        }
        *(float4*)(g_y + (size_t)warp * D + lane * 4) = acc;
        if (lane == 0) g_sg[warp] = denom * inv;
    } else {
        // ---- Rare slow path (len > 32): recompute gates in pass B ----
        for (int r = 0; r < len; ++r) {
            float4 v = *(const float4*)(xb + (size_t)r * D);
            float p = warp_sum(dot4(v, wg));
            denom += w[r0 + r] * expf(p + bg0);
        }
        float inv = 1.f / (denom + EPS);
        float4 acc = make_float4(0.f,0.f,0.f,0.f);
        for (int r = 0; r < len; ++r) {
            float4 v = *(const float4*)(xb + (size_t)r * D);
            float p = warp_sum(dot4(v, wg));
            float c = w[r0 + r] * expf(p + bg0) * inv;
            acc.x += c * v.x; acc.y += c * v.y;
            acc.z += c * v.z; acc.w += c * v.w;
        }
        *(float4*)(g_y + (size_t)warp * D + lane * 4) = acc;
        if (lane == 0) g_sg[warp] = denom * inv;
    }
}

// ---------------------------------------------------------------------------
// Kernel 3: out[S,128] = y @ Wm + sg (x) bm    (tf32 mma.sync, fp32 accum)
// Block: 256 threads, tile M=128 N=128, K tiled by 32.
// Warp tile 32x64 (2 m-frags x 8 n-frags of m16n8k8).
// ---------------------------------------------------------------------------
#define BM 128
#define BN 128
#define BK 32

__device__ __forceinline__ uint32_t f2tf32(float f) {
    uint32_t r;
    asm("cvt.rna.tf32.f32 %0, %1;" : "=r"(r) : "f"(f));
    return r;
}

__device__ __forceinline__ void mma_tf32(float* c, const uint32_t* a, const uint32_t* b) {
    asm volatile(
        "mma.sync.aligned.m16n8k8.row.col.f32.tf32.tf32.f32 "
        "{%0,%1,%2,%3}, {%4,%5,%6,%7}, {%8,%9}, {%0,%1,%2,%3};\n"
        : "+f"(c[0]), "+f"(c[1]), "+f"(c[2]), "+f"(c[3])
        : "r"(a[0]), "r"(a[1]), "r"(a[2]), "r"(a[3]), "r"(b[0]), "r"(b[1]));
}

__global__ void __launch_bounds__(256)
gemm_kernel(const float* __restrict__ Wm,
            const float* __restrict__ bm,
            float* __restrict__ out, int S) {
    __shared__ float yS[BM][BK + 4];   // +4 pad: conflict-free frag loads
    __shared__ float wS[BK][BN + 4];

    int tid  = threadIdx.x;
    int wid  = tid >> 5;
    int lane = tid & 31;
    int warp_m = wid & 3;       // 4 warps along M (32 rows each)
    int warp_n = wid >> 2;      // 2 warps along N (64 cols each)
    int grp = lane >> 2;        // groupID 0..7
    int tg  = lane & 3;         // thread-in-group 0..3
    int rowbase = blockIdx.x * BM;

    float c[2][8][4];
    #pragma unroll
    for (int mf = 0; mf < 2; ++mf)
        #pragma unroll
        for (int nf = 0; nf < 8; ++nf)
            #pragma unroll
            for (int i = 0; i < 4; ++i) c[mf][nf][i] = 0.f;

    for (int kt = 0; kt < D; kt += BK) {
        __syncthreads();
        // Stage y tile [128 x 32]
        {
            int r = tid >> 3;          // 0..31
            int q = tid & 7;           // float4 slot 0..7
            #pragma unroll
            for (int it = 0; it < 4; ++it) {
                int row  = r + it * 32;
                int grow = rowbase + row;
                float4 v = make_float4(0.f,0.f,0.f,0.f);
                if (grow < S)
                    v = *(const float4*)(g_y + (size_t)grow * D + kt + q * 4);
                *(float4*)&yS[row][q * 4] = v;
            }
            // Stage Wm tile [32 x 128]
            int k = tid >> 3;          // 0..31
            #pragma unroll
            for (int it = 0; it < 4; ++it) {
                int q = (tid & 7) + it * 8;
                *(float4*)&wS[k][q * 4] =
                    *(const float4*)(Wm + (size_t)(kt + k) * D + q * 4);
            }
        }
        __syncthreads();

        #pragma unroll
        for (int ks = 0; ks < BK; ks += 8) {
            uint32_t a[2][4];
            uint32_t b[8][2];
            #pragma unroll
            for (int mf = 0; mf < 2; ++mf) {
                int r = warp_m * 32 + mf * 16;
                a[mf][0] = f2tf32(yS[r + grp    ][ks + tg    ]);
                a[mf][1] = f2tf32(yS[r + grp + 8][ks + tg    ]);
                a[mf][2] = f2tf32(yS[r + grp    ][ks + tg + 4]);
                a[mf][3] = f2tf32(yS[r + grp + 8][ks + tg + 4]);
            }
            #pragma unroll
            for (int nf = 0; nf < 8; ++nf) {
                int col = warp_n * 64 + nf * 8 + grp;
                b[nf][0] = f2tf32(wS[ks + tg    ][col]);
                b[nf][1] = f2tf32(wS[ks + tg + 4][col]);
            }
            #pragma unroll
            for (int mf = 0; mf < 2; ++mf)
                #pragma unroll
                for (int nf = 0; nf < 8; ++nf)
                    mma_tf32(c[mf][nf], a[mf], b[nf]);
        }
    }

    // Epilogue: out = c + sg[row] * bm[col]
    #pragma unroll
    for (int mf = 0; mf < 2; ++mf) {
        int row0 = rowbase + warp_m * 32 + mf * 16 + grp;
        int row1 = row0 + 8;
        float sgA = (row0 < S) ? g_sg[row0] : 0.f;
        float sgB = (row1 < S) ? g_sg[row1] : 0.f;
        #pragma unroll
        for (int nf = 0; nf < 8; ++nf) {
            int col = warp_n * 64 + nf * 8 + tg * 2;
            float b0 = bm[col], b1 = bm[col + 1];
            if (row0 < S) {
                float2 o;
                o.x = c[mf][nf][0] + sgA * b0;
                o.y = c[mf][nf][1] + sgA * b1;
                *(float2*)(out + (size_t)row0 * D + col) = o;
            }
            if (row1 < S) {
                float2 o;
                o.x = c[mf][nf][2] + sgB * b0;
                o.y = c[mf][nf][3] + sgB * b1;
                *(float2*)(out + (size_t)row1 * D + col) = o;
            }
        }
    }
}

// ---------------------------------------------------------------------------
extern "C" void kernel_launch(void* const* d_in, const int* in_sizes, int n_in,
                              void* d_out, int out_size) {
    const float* x   = (const float*)d_in[0];
    const int*   idx = (const int*)  d_in[1];
    const float* w   = (const float*)d_in[2];
    const float* Wg  = (const float*)d_in[3];
    const float* bg  = (const float*)d_in[4];
    const float* Wm  = (const float*)d_in[5];
    const float* bm  = (const float*)d_in[6];
    float* out = (float*)d_out;

    int N = in_sizes[1];          // index element count
    int S = out_size / D;         // segments

    seg_starts_kernel<<<(N + 255) / 256, 256>>>(idx, N, S);

    // one warp per segment
    long long total_threads = (long long)S * 32;
    int agg_blocks = (int)((total_threads + 255) / 256);
    agg_kernel<<<agg_blocks, 256>>>(x, w, Wg, bg, S);

    gemm_kernel<<<(S + BM - 1) / BM, 256>>>(Wm, bm, out, S);
}

// round 3
// speedup vs baseline: 1.1341x; 1.1341x over previous
#include <cuda_runtime.h>
#include <cstdint>
#include <math.h>

#define D    128
#define S_MAX 125000
#define EPS  1e-13f

// Scratch (static device globals -- no allocation)
__device__ float g_y[(size_t)S_MAX * D];   // 64 MB: per-segment weighted (unnormalized->normalized) sum of x
__device__ float g_sg[S_MAX];              // per-segment sum of normalized gates
__device__ int   g_starts[S_MAX + 1];      // segment start offsets

// ---------------------------------------------------------------------------
// Kernel 1: segment start offsets from the sorted index array.
// ---------------------------------------------------------------------------
__global__ void seg_starts_kernel(const int* __restrict__ idx, int N, int S) {
    int n = blockIdx.x * blockDim.x + threadIdx.x;
    if (n >= N) return;
    int cur  = idx[n];
    int prev = (n == 0) ? -1 : idx[n - 1];
    for (int s = prev + 1; s <= cur; ++s) g_starts[s] = n;
    if (n == N - 1) {
        for (int s = cur + 1; s <= S; ++s) g_starts[s] = N;
    }
}

__device__ __forceinline__ float warp_sum(float v) {
    v += __shfl_xor_sync(0xffffffffu, v, 16);
    v += __shfl_xor_sync(0xffffffffu, v, 8);
    v += __shfl_xor_sync(0xffffffffu, v, 4);
    v += __shfl_xor_sync(0xffffffffu, v, 2);
    v += __shfl_xor_sync(0xffffffffu, v, 1);
    return v;
}

__device__ __forceinline__ float dot4(float4 a, float4 b) {
    return a.x * b.x + a.y * b.y + a.z * b.z + a.w * b.w;
}

// ---------------------------------------------------------------------------
// Kernel 2: SINGLE-PASS fused gate + weighted segment aggregation.
// Key identity: y_s = (Sum_r g_r * x_r) / denom  -- normalization factors out,
// so each x row is loaded exactly ONCE: compute g_r from the row that is
// still live in registers, accumulate unnormalized, scale at the end.
// One warp per segment; lane l covers columns [4l, 4l+4).
// 4 rows in flight per iteration for memory-level parallelism.
// ---------------------------------------------------------------------------
__global__ void __launch_bounds__(256)
agg_kernel(const float* __restrict__ x,
           const float* __restrict__ w,
           const float* __restrict__ Wg,
           const float* __restrict__ bgp,
           int S) {
    int warp = (int)((blockIdx.x * (unsigned)blockDim.x + threadIdx.x) >> 5);
    if (warp >= S) return;
    int lane = threadIdx.x & 31;

    int r0 = g_starts[warp];
    int r1 = g_starts[warp + 1];
    int len = r1 - r0;

    float4 wg  = *(const float4*)(Wg + lane * 4);
    float  bg0 = bgp[0];
    const float* xb = x + (size_t)r0 * D + lane * 4;

    float  denom = 0.f;
    float4 acc = make_float4(0.f, 0.f, 0.f, 0.f);

    int base = 0;
    // Main loop: 4 full rows per iteration (no predication on the hot path)
    for (; base + 4 <= len; base += 4) {
        float4 v0 = *(const float4*)(xb + (size_t)(base + 0) * D);
        float4 v1 = *(const float4*)(xb + (size_t)(base + 1) * D);
        float4 v2 = *(const float4*)(xb + (size_t)(base + 2) * D);
        float4 v3 = *(const float4*)(xb + (size_t)(base + 3) * D);
        float w0 = w[r0 + base + 0];
        float w1 = w[r0 + base + 1];
        float w2 = w[r0 + base + 2];
        float w3 = w[r0 + base + 3];
        float p0 = warp_sum(dot4(v0, wg));
        float p1 = warp_sum(dot4(v1, wg));
        float p2 = warp_sum(dot4(v2, wg));
        float p3 = warp_sum(dot4(v3, wg));
        float g0 = w0 * __expf(p0 + bg0);
        float g1 = w1 * __expf(p1 + bg0);
        float g2 = w2 * __expf(p2 + bg0);
        float g3 = w3 * __expf(p3 + bg0);
        denom += (g0 + g1) + (g2 + g3);
        acc.x += g0 * v0.x + g1 * v1.x + g2 * v2.x + g3 * v3.x;
        acc.y += g0 * v0.y + g1 * v1.y + g2 * v2.y + g3 * v3.y;
        acc.z += g0 * v0.z + g1 * v1.z + g2 * v2.z + g3 * v3.z;
        acc.w += g0 * v0.w + g1 * v1.w + g2 * v2.w + g3 * v3.w;
    }
    // Remainder (0-3 rows)
    for (; base < len; ++base) {
        float4 v = *(const float4*)(xb + (size_t)base * D);
        float  p = warp_sum(dot4(v, wg));
        float  g = w[r0 + base] * __expf(p + bg0);
        denom += g;
        acc.x += g * v.x; acc.y += g * v.y;
        acc.z += g * v.z; acc.w += g * v.w;
    }

    float inv = 1.f / (denom + EPS);
    float4 o;
    o.x = acc.x * inv; o.y = acc.y * inv;
    o.z = acc.z * inv; o.w = acc.w * inv;
    *(float4*)(g_y + (size_t)warp * D + lane * 4) = o;
    if (lane == 0) g_sg[warp] = denom * inv;
}

// ---------------------------------------------------------------------------
// Kernel 3: out[S,128] = y @ Wm + sg (x) bm    (tf32 mma.sync, fp32 accum)
// ---------------------------------------------------------------------------
#define BM 128
#define BN 128
#define BK 32

__device__ __forceinline__ uint32_t f2tf32(float f) {
    uint32_t r;
    asm("cvt.rna.tf32.f32 %0, %1;" : "=r"(r) : "f"(f));
    return r;
}

__device__ __forceinline__ void mma_tf32(float* c, const uint32_t* a, const uint32_t* b) {
    asm volatile(
        "mma.sync.aligned.m16n8k8.row.col.f32.tf32.tf32.f32 "
        "{%0,%1,%2,%3}, {%4,%5,%6,%7}, {%8,%9}, {%0,%1,%2,%3};\n"
        : "+f"(c[0]), "+f"(c[1]), "+f"(c[2]), "+f"(c[3])
        : "r"(a[0]), "r"(a[1]), "r"(a[2]), "r"(a[3]), "r"(b[0]), "r"(b[1]));
}

__global__ void __launch_bounds__(256)
gemm_kernel(const float* __restrict__ Wm,
            const float* __restrict__ bm,
            float* __restrict__ out, int S) {
    __shared__ float yS[BM][BK + 4];
    __shared__ float wS[BK][BN + 4];

    int tid  = threadIdx.x;
    int wid  = tid >> 5;
    int lane = tid & 31;
    int warp_m = wid & 3;
    int warp_n = wid >> 2;
    int grp = lane >> 2;
    int tg  = lane & 3;
    int rowbase = blockIdx.x * BM;

    float c[2][8][4];
    #pragma unroll
    for (int mf = 0; mf < 2; ++mf)
        #pragma unroll
        for (int nf = 0; nf < 8; ++nf)
            #pragma unroll
            for (int i = 0; i < 4; ++i) c[mf][nf][i] = 0.f;

    for (int kt = 0; kt < D; kt += BK) {
        __syncthreads();
        {
            int r = tid >> 3;
            int q = tid & 7;
            #pragma unroll
            for (int it = 0; it < 4; ++it) {
                int row  = r + it * 32;
                int grow = rowbase + row;
                float4 v = make_float4(0.f,0.f,0.f,0.f);
                if (grow < S)
                    v = *(const float4*)(g_y + (size_t)grow * D + kt + q * 4);
                *(float4*)&yS[row][q * 4] = v;
            }
            int k = tid >> 3;
            #pragma unroll
            for (int it = 0; it < 4; ++it) {
                int qq = (tid & 7) + it * 8;
                *(float4*)&wS[k][qq * 4] =
                    *(const float4*)(Wm + (size_t)(kt + k) * D + qq * 4);
            }
        }
        __syncthreads();

        #pragma unroll
        for (int ks = 0; ks < BK; ks += 8) {
            uint32_t a[2][4];
            uint32_t b[8][2];
            #pragma unroll
            for (int mf = 0; mf < 2; ++mf) {
                int r = warp_m * 32 + mf * 16;
                a[mf][0] = f2tf32(yS[r + grp    ][ks + tg    ]);
                a[mf][1] = f2tf32(yS[r + grp + 8][ks + tg    ]);
                a[mf][2] = f2tf32(yS[r + grp    ][ks + tg + 4]);
                a[mf][3] = f2tf32(yS[r + grp + 8][ks + tg + 4]);
            }
            #pragma unroll
            for (int nf = 0; nf < 8; ++nf) {
                int col = warp_n * 64 + nf * 8 + grp;
                b[nf][0] = f2tf32(wS[ks + tg    ][col]);
                b[nf][1] = f2tf32(wS[ks + tg + 4][col]);
            }
            #pragma unroll
            for (int mf = 0; mf < 2; ++mf)
                #pragma unroll
                for (int nf = 0; nf < 8; ++nf)
                    mma_tf32(c[mf][nf], a[mf], b[nf]);
        }
    }

    #pragma unroll
    for (int mf = 0; mf < 2; ++mf) {
        int row0 = rowbase + warp_m * 32 + mf * 16 + grp;
        int row1 = row0 + 8;
        float sgA = (row0 < S) ? g_sg[row0] : 0.f;
        float sgB = (row1 < S) ? g_sg[row1] : 0.f;
        #pragma unroll
        for (int nf = 0; nf < 8; ++nf) {
            int col = warp_n * 64 + nf * 8 + tg * 2;
            float b0 = bm[col], b1 = bm[col + 1];
            if (row0 < S) {
                float2 o;
                o.x = c[mf][nf][0] + sgA * b0;
                o.y = c[mf][nf][1] + sgA * b1;
                *(float2*)(out + (size_t)row0 * D + col) = o;
            }
            if (row1 < S) {
                float2 o;
                o.x = c[mf][nf][2] + sgB * b0;
                o.y = c[mf][nf][3] + sgB * b1;
                *(float2*)(out + (size_t)row1 * D + col) = o;
            }
        }
    }
}

// ---------------------------------------------------------------------------
extern "C" void kernel_launch(void* const* d_in, const int* in_sizes, int n_in,
                              void* d_out, int out_size) {
    const float* x   = (const float*)d_in[0];
    const int*   idx = (const int*)  d_in[1];
    const float* w   = (const float*)d_in[2];
    const float* Wg  = (const float*)d_in[3];
    const float* bg  = (const float*)d_in[4];
    const float* Wm  = (const float*)d_in[5];
    const float* bm  = (const float*)d_in[6];
    float* out = (float*)d_out;

    int N = in_sizes[1];
    int S = out_size / D;

    seg_starts_kernel<<<(N + 255) / 256, 256>>>(idx, N, S);

    long long total_threads = (long long)S * 32;
    int agg_blocks = (int)((total_threads + 255) / 256);
    agg_kernel<<<agg_blocks, 256>>>(x, w, Wg, bg, S);

    gemm_kernel<<<(S + BM - 1) / BM, 256>>>(Wm, bm, out, S);
}